// round 11
// baseline (speedup 1.0000x reference)
#include <cuda_runtime.h>
#include <cuda_fp16.h>

// BlurNet: fake_B = w * mean_k bilinear(fake_S, pix + t_k*20*blurmap) + bias
//          offsets_flat[b, 2k+c] = t_k * 20 * blurmap[b, c],  t_k = (7-k)/7
// B=8, C=3, H=W=256. Output: fake_B (B*3*H*W) then offsets (B*30*H*W), f32.
//
// R11 = R10 (64x32 tile, 512 thr, 2 CTAs/SM, fp16 pair-dup gather) with the
// 30 offset STG.32/px EVICTED from the blur loop into 40 dedicated writer
// CTAs appended to the same launch (256 blur + 40 writer = 296 = exactly the
// 2x148 CTA capacity). Writer CTAs are float4-streaming, L2-bound (~7us),
// fully hidden under the blur CTAs' LDS-bound ~27us. Removes ~35% of the
// blur warps' MIO work (STG shares the LSU dispatch path with LDS).

#define H 256
#define W 256
#define HW (H * W)
#define BATCH 8
#define TX 64
#define TY 32
#define HALO 20
#define TDX (TX + 2 * HALO)      // 104
#define TDY (TY + 2 * HALO)      // 72
#define NTHREADS 512
#define BLUR_CTAS 256            // 4 x 8 x 8
#define OFF_CTAS 40
#define TOTAL_CTAS (BLUR_CTAS + OFF_CTAS)

__global__ __launch_bounds__(NTHREADS, 2)
void blurnet_kernel(const float* __restrict__ fake_S,
                    const float* __restrict__ blurmap,
                    const float* __restrict__ weight,
                    const float* __restrict__ bias,
                    float* __restrict__ out_fb,
                    float* __restrict__ out_off)
{
    extern __shared__ __align__(16) unsigned char smem_raw[];
    uint2*   Ap = (uint2*)smem_raw;                         // 72*104*8 = 59904 B
    __half2* Cp = (__half2*)(smem_raw + TDY * TDX * 8);     // 72*104*4 = 29952 B

    const int bid = blockIdx.x;
    const int tid = threadIdx.x;

    // ================= Offsets-writer role =================
    if (bid >= BLUR_CTAS) {
        // offsets region as float4: plane = (b*30 + 2k + c), pos in [0, HW/4)
        const int rid = bid - BLUR_CTAS;
        const int N4 = BATCH * 30 * (HW / 4);          // 3,932,160
        const float4* bm4 = (const float4*)blurmap;
        float4* off4 = (float4*)out_off;
        #pragma unroll 1
        for (int i4 = rid * NTHREADS + tid; i4 < N4; i4 += OFF_CTAS * NTHREADS) {
            int plane = i4 >> 14;                      // HW/4 = 16384
            int pos   = i4 & 16383;
            int b     = plane / 30;
            int ch    = plane - b * 30;
            int k     = ch >> 1;
            int c     = ch & 1;
            float t   = (float)(7 - k) * (1.0f / 7.0f);
            float4 v  = bm4[(b * 2 + c) * (HW / 4) + pos];
            // same op order as reference: ob = 20*bm, then t*ob
            float4 r;
            r.x = t * (20.0f * v.x);
            r.y = t * (20.0f * v.y);
            r.z = t * (20.0f * v.z);
            r.w = t * (20.0f * v.w);
            off4[i4] = r;
        }
        return;
    }

    // ================= Blur role =================
    const int bx = bid & 3;
    const int by = (bid >> 2) & 7;
    const int b  = bid >> 5;
    const int tx0 = bx * TX;
    const int ty0 = by * TY;

    const float* img  = fake_S  + (size_t)b * 3 * HW;
    const float* bm   = blurmap + (size_t)b * 2 * HW;
    float*       fb   = out_fb  + (size_t)b * 3 * HW;

    // ---- Halo fill: R3-proven scalar path ----
    #pragma unroll 3
    for (int p = tid; p < TDY * TDX; p += NTHREADS) {
        int r  = p / TDX;
        int cc = p - r * TDX;
        int gy = ty0 - HALO + r;
        int gx = tx0 - HALO + cc;
        float v0 = 0.f, v1 = 0.f, v2 = 0.f;   // (gy, gx)
        float u0 = 0.f, u1 = 0.f, u2 = 0.f;   // (gy, gx+1)
        bool rowok = (unsigned)gy < (unsigned)H;
        if (rowok && (unsigned)gx < (unsigned)W) {
            int gi = gy * W + gx;
            v0 = __ldg(img + gi);
            v1 = __ldg(img + gi + HW);
            v2 = __ldg(img + gi + 2 * HW);
        }
        if (rowok && (unsigned)(gx + 1) < (unsigned)W) {
            int gi = gy * W + gx + 1;
            u0 = __ldg(img + gi);
            u1 = __ldg(img + gi + HW);
            u2 = __ldg(img + gi + 2 * HW);
        }
        __half2 lo = __floats2half2_rn(v0, v1);
        __half2 hi = __floats2half2_rn(u0, u1);
        uint2 w;
        w.x = *(unsigned int*)&lo;
        w.y = *(unsigned int*)&hi;
        Ap[p] = w;
        Cp[p] = __floats2half2_rn(v2, u2);
    }
    __syncthreads();

    const float wgt = __ldg(weight) * (1.0f / 15.0f);
    const float bs  = __ldg(bias);

    // ---- Blur loop (no offset stores — writer CTAs own them) ----
    #pragma unroll 1
    for (int i = 0; i < (TX * TY) / NTHREADS; i++) {
        int p  = i * NTHREADS + tid;
        int yl = p >> 6;              // 0..31
        int xl = p & 63;              // 0..63
        int gy = ty0 + yl;
        int gx = tx0 + xl;
        int gidx = gy * W + gx;

        float ob0 = 20.0f * __ldg(bm + gidx);        // dy scale (ch0)
        float ob1 = 20.0f * __ldg(bm + gidx + HW);   // dx scale (ch1)

        // k = 7 (t = 0): exact center sample
        int cbase = (yl + HALO) * TDX + (xl + HALO);
        uint2 cw = Ap[cbase];
        float2 cl = __half22float2(*(__half2*)&cw.x);
        float2 cz = __half22float2(Cp[cbase]);
        float s0 = cl.x, s1 = cl.y, s2 = cz.x;

        #pragma unroll
        for (int k = 0; k < 15; k++) {
            if (k == 7) continue;
            const float t = (float)(7 - k) / 7.0f;   // compile-time constant
            float oy = t * ob0;
            float ox = t * ob1;

            float fy  = (float)gy + oy;              // global coords = ref rounding
            float fx  = (float)gx + ox;
            float fy0 = floorf(fy);
            float fx0 = floorf(fx);
            float tyf = fy - fy0;
            float txf = fx - fx0;
            int iy = (int)fy0 - ty0 + HALO;
            int ix = (int)fx0 - tx0 + HALO;
            int base2 = iy * TDX + ix;

            uint2   w0 = Ap[base2];           // row y0: (c0,c1)@x0,x1
            uint2   w1 = Ap[base2 + TDX];     // row y1
            __half2 z0 = Cp[base2];           // c2@(x0,x1), row y0
            __half2 z1 = Cp[base2 + TDX];     // row y1

            float2 p00 = __half22float2(*(__half2*)&w0.x);
            float2 p01 = __half22float2(*(__half2*)&w0.y);
            float2 p10 = __half22float2(*(__half2*)&w1.x);
            float2 p11 = __half22float2(*(__half2*)&w1.y);
            float2 q0  = __half22float2(z0);
            float2 q1  = __half22float2(z1);

            float w11f = tyf * txf;
            float w10f = tyf - w11f;
            float w01f = txf - w11f;
            float w00f = 1.0f - tyf - txf + w11f;

            s0 = fmaf(w00f, p00.x, s0); s0 = fmaf(w01f, p01.x, s0);
            s0 = fmaf(w10f, p10.x, s0); s0 = fmaf(w11f, p11.x, s0);
            s1 = fmaf(w00f, p00.y, s1); s1 = fmaf(w01f, p01.y, s1);
            s1 = fmaf(w10f, p10.y, s1); s1 = fmaf(w11f, p11.y, s1);
            s2 = fmaf(w00f, q0.x, s2);  s2 = fmaf(w01f, q0.y, s2);
            s2 = fmaf(w10f, q1.x, s2);  s2 = fmaf(w11f, q1.y, s2);
        }

        fb[gidx]          = fmaf(wgt, s0, bs);
        fb[gidx + HW]     = fmaf(wgt, s1, bs);
        fb[gidx + 2 * HW] = fmaf(wgt, s2, bs);
    }
}

extern "C" void kernel_launch(void* const* d_in, const int* in_sizes, int n_in,
                              void* d_out, int out_size)
{
    const float* fake_S  = (const float*)d_in[0];
    const float* blurmap = (const float*)d_in[1];
    const float* weight  = (const float*)d_in[2];
    const float* bias    = (const float*)d_in[3];

    float* out_fb  = (float*)d_out;
    float* out_off = (float*)d_out + (size_t)BATCH * 3 * HW;

    const int smem = TDY * TDX * 12;   // 89,856 B
    static bool configured = false;
    if (!configured) {
        cudaFuncSetAttribute(blurnet_kernel,
                             cudaFuncAttributeMaxDynamicSharedMemorySize, smem);
        configured = true;
    }

    blurnet_kernel<<<TOTAL_CTAS, NTHREADS, smem>>>(fake_S, blurmap, weight,
                                                   bias, out_fb, out_off);
}

// round 12
// speedup vs baseline: 1.5263x; 1.5263x over previous
#include <cuda_runtime.h>
#include <cuda_fp16.h>

// BlurNet: fake_B = w * mean_k bilinear(fake_S, pix + t_k*20*blurmap) + bias
//          offsets_flat[b, 2k+c] = t_k * 20 * blurmap[b, c],  t_k = (7-k)/7
// B=8, C=3, H=W=256. Output: fake_B (B*3*H*W) then offsets (B*30*H*W), f32.
//
// R12 = R11 with the writer-CTA dataflow fixed. R11's writer did 192 serial
// dependent LDG->STG per thread (MLP=1, ~600cyc each => 65us critical path —
// the measured 2x regression). Now one work item = one (b,c,pos4):
// 1 LDG.128 -> 15 independent STG.128 (all k-planes reuse the load). 13 iters
// x 600cyc = ~4.4us, hidden under the blur CTAs' ~27us.
// Blur role identical to R10 minus the interleaved offset STGs.

#define H 256
#define W 256
#define HW (H * W)
#define BATCH 8
#define TX 64
#define TY 32
#define HALO 20
#define TDX (TX + 2 * HALO)      // 104
#define TDY (TY + 2 * HALO)      // 72
#define NTHREADS 512
#define BLUR_CTAS 256            // 4 x 8 x 8
#define OFF_CTAS 40
#define TOTAL_CTAS (BLUR_CTAS + OFF_CTAS)
#define NPOS (HW / 4)            // 16384 float4 per plane

__global__ __launch_bounds__(NTHREADS, 2)
void blurnet_kernel(const float* __restrict__ fake_S,
                    const float* __restrict__ blurmap,
                    const float* __restrict__ weight,
                    const float* __restrict__ bias,
                    float* __restrict__ out_fb,
                    float* __restrict__ out_off)
{
    extern __shared__ __align__(16) unsigned char smem_raw[];
    uint2*   Ap = (uint2*)smem_raw;                         // 72*104*8 = 59904 B
    __half2* Cp = (__half2*)(smem_raw + TDY * TDX * 8);     // 72*104*4 = 29952 B

    const int bid = blockIdx.x;
    const int tid = threadIdx.x;

    // ================= Offsets-writer role =================
    if (bid >= BLUR_CTAS) {
        const int rid = bid - BLUR_CTAS;
        const int NITEMS = BATCH * 2 * NPOS;           // 262,144
        const float4* bm4 = (const float4*)blurmap;
        float4* off4 = (float4*)out_off;
        #pragma unroll 1
        for (int it = rid * NTHREADS + tid; it < NITEMS; it += OFF_CTAS * NTHREADS) {
            int bc  = it >> 14;                        // b*2 + c
            int pos = it & (NPOS - 1);
            int b   = bc >> 1;
            int c   = bc & 1;
            float4 v = bm4[it];                        // blurmap flat = (b*2+c)*NPOS+pos
            float4 ob;                                 // ob = 20*bm (ref op order)
            ob.x = 20.0f * v.x;
            ob.y = 20.0f * v.y;
            ob.z = 20.0f * v.z;
            ob.w = 20.0f * v.w;
            float4* dst = off4 + ((size_t)(b * 30 + c) * NPOS + pos);
            #pragma unroll
            for (int k = 0; k < 15; k++) {
                const float t = (float)(7 - k) / 7.0f;
                float4 r;
                r.x = t * ob.x;
                r.y = t * ob.y;
                r.z = t * ob.z;
                r.w = t * ob.w;
                dst[2 * k * NPOS] = r;                 // plane b*30+2k+c
            }
        }
        return;
    }

    // ================= Blur role =================
    const int bx = bid & 3;
    const int by = (bid >> 2) & 7;
    const int b  = bid >> 5;
    const int tx0 = bx * TX;
    const int ty0 = by * TY;

    const float* img  = fake_S  + (size_t)b * 3 * HW;
    const float* bm   = blurmap + (size_t)b * 2 * HW;
    float*       fb   = out_fb  + (size_t)b * 3 * HW;

    // ---- Halo fill: R3-proven scalar path ----
    #pragma unroll 3
    for (int p = tid; p < TDY * TDX; p += NTHREADS) {
        int r  = p / TDX;
        int cc = p - r * TDX;
        int gy = ty0 - HALO + r;
        int gx = tx0 - HALO + cc;
        float v0 = 0.f, v1 = 0.f, v2 = 0.f;   // (gy, gx)
        float u0 = 0.f, u1 = 0.f, u2 = 0.f;   // (gy, gx+1)
        bool rowok = (unsigned)gy < (unsigned)H;
        if (rowok && (unsigned)gx < (unsigned)W) {
            int gi = gy * W + gx;
            v0 = __ldg(img + gi);
            v1 = __ldg(img + gi + HW);
            v2 = __ldg(img + gi + 2 * HW);
        }
        if (rowok && (unsigned)(gx + 1) < (unsigned)W) {
            int gi = gy * W + gx + 1;
            u0 = __ldg(img + gi);
            u1 = __ldg(img + gi + HW);
            u2 = __ldg(img + gi + 2 * HW);
        }
        __half2 lo = __floats2half2_rn(v0, v1);
        __half2 hi = __floats2half2_rn(u0, u1);
        uint2 w;
        w.x = *(unsigned int*)&lo;
        w.y = *(unsigned int*)&hi;
        Ap[p] = w;
        Cp[p] = __floats2half2_rn(v2, u2);
    }
    __syncthreads();

    const float wgt = __ldg(weight) * (1.0f / 15.0f);
    const float bs  = __ldg(bias);

    // ---- Blur loop (no offset stores — writer CTAs own them) ----
    #pragma unroll 1
    for (int i = 0; i < (TX * TY) / NTHREADS; i++) {
        int p  = i * NTHREADS + tid;
        int yl = p >> 6;              // 0..31
        int xl = p & 63;              // 0..63
        int gy = ty0 + yl;
        int gx = tx0 + xl;
        int gidx = gy * W + gx;

        float ob0 = 20.0f * __ldg(bm + gidx);        // dy scale (ch0)
        float ob1 = 20.0f * __ldg(bm + gidx + HW);   // dx scale (ch1)

        // k = 7 (t = 0): exact center sample
        int cbase = (yl + HALO) * TDX + (xl + HALO);
        uint2 cw = Ap[cbase];
        float2 cl = __half22float2(*(__half2*)&cw.x);
        float2 cz = __half22float2(Cp[cbase]);
        float s0 = cl.x, s1 = cl.y, s2 = cz.x;

        #pragma unroll
        for (int k = 0; k < 15; k++) {
            if (k == 7) continue;
            const float t = (float)(7 - k) / 7.0f;   // compile-time constant
            float oy = t * ob0;
            float ox = t * ob1;

            float fy  = (float)gy + oy;              // global coords = ref rounding
            float fx  = (float)gx + ox;
            float fy0 = floorf(fy);
            float fx0 = floorf(fx);
            float tyf = fy - fy0;
            float txf = fx - fx0;
            int iy = (int)fy0 - ty0 + HALO;
            int ix = (int)fx0 - tx0 + HALO;
            int base2 = iy * TDX + ix;

            uint2   w0 = Ap[base2];           // row y0: (c0,c1)@x0,x1
            uint2   w1 = Ap[base2 + TDX];     // row y1
            __half2 z0 = Cp[base2];           // c2@(x0,x1), row y0
            __half2 z1 = Cp[base2 + TDX];     // row y1

            float2 p00 = __half22float2(*(__half2*)&w0.x);
            float2 p01 = __half22float2(*(__half2*)&w0.y);
            float2 p10 = __half22float2(*(__half2*)&w1.x);
            float2 p11 = __half22float2(*(__half2*)&w1.y);
            float2 q0  = __half22float2(z0);
            float2 q1  = __half22float2(z1);

            float w11f = tyf * txf;
            float w10f = tyf - w11f;
            float w01f = txf - w11f;
            float w00f = 1.0f - tyf - txf + w11f;

            s0 = fmaf(w00f, p00.x, s0); s0 = fmaf(w01f, p01.x, s0);
            s0 = fmaf(w10f, p10.x, s0); s0 = fmaf(w11f, p11.x, s0);
            s1 = fmaf(w00f, p00.y, s1); s1 = fmaf(w01f, p01.y, s1);
            s1 = fmaf(w10f, p10.y, s1); s1 = fmaf(w11f, p11.y, s1);
            s2 = fmaf(w00f, q0.x, s2);  s2 = fmaf(w01f, q0.y, s2);
            s2 = fmaf(w10f, q1.x, s2);  s2 = fmaf(w11f, q1.y, s2);
        }

        fb[gidx]          = fmaf(wgt, s0, bs);
        fb[gidx + HW]     = fmaf(wgt, s1, bs);
        fb[gidx + 2 * HW] = fmaf(wgt, s2, bs);
    }
}

extern "C" void kernel_launch(void* const* d_in, const int* in_sizes, int n_in,
                              void* d_out, int out_size)
{
    const float* fake_S  = (const float*)d_in[0];
    const float* blurmap = (const float*)d_in[1];
    const float* weight  = (const float*)d_in[2];
    const float* bias    = (const float*)d_in[3];

    float* out_fb  = (float*)d_out;
    float* out_off = (float*)d_out + (size_t)BATCH * 3 * HW;

    const int smem = TDY * TDX * 12;   // 89,856 B
    static bool configured = false;
    if (!configured) {
        cudaFuncSetAttribute(blurnet_kernel,
                             cudaFuncAttributeMaxDynamicSharedMemorySize, smem);
        configured = true;
    }

    blurnet_kernel<<<TOTAL_CTAS, NTHREADS, smem>>>(fake_S, blurmap, weight,
                                                   bias, out_fb, out_off);
}

// round 13
// speedup vs baseline: 1.9313x; 1.2653x over previous
#include <cuda_runtime.h>
#include <cuda_fp16.h>

// BlurNet: fake_B = w * mean_k bilinear(fake_S, pix + t_k*20*blurmap) + bias
//          offsets_flat[b, 2k+c] = t_k * 20 * blurmap[b, c],  t_k = (7-k)/7
// B=8, C=3, H=W=256. Output: fake_B (B*3*H*W) then offsets (B*30*H*W), f32.
//
// R13 = R10 (best: 64x32 tile, 512 thr, 2 CTAs/SM, fp16 pair-dup gather,
// interleaved offset STGs) + half2 interpolation: x- and y-lerp in HFMA2
// before converting, 12 F2F + 12 FFMA -> 6 HFMA-class + 4 F2F + 5 FADD/FFMA
// per sample. Eviction/phase-separation lines abandoned (R4/7/8/11/12 data).

#define H 256
#define W 256
#define HW (H * W)
#define BATCH 8
#define TX 64
#define TY 32
#define HALO 20
#define TDX (TX + 2 * HALO)      // 104
#define TDY (TY + 2 * HALO)      // 72
#define NTHREADS 512

__global__ __launch_bounds__(NTHREADS, 2)
void blurnet_kernel(const float* __restrict__ fake_S,
                    const float* __restrict__ blurmap,
                    const float* __restrict__ weight,
                    const float* __restrict__ bias,
                    float* __restrict__ out_fb,
                    float* __restrict__ out_off)
{
    extern __shared__ __align__(16) unsigned char smem_raw[];
    uint2*   Ap = (uint2*)smem_raw;                         // 72*104*8 = 59904 B
    __half2* Cp = (__half2*)(smem_raw + TDY * TDX * 8);     // 72*104*4 = 29952 B

    const int tx0 = blockIdx.x * TX;
    const int ty0 = blockIdx.y * TY;
    const int b   = blockIdx.z;
    const int tid = threadIdx.x;

    const float* img  = fake_S  + (size_t)b * 3 * HW;
    const float* bm   = blurmap + (size_t)b * 2 * HW;
    float*       fb   = out_fb  + (size_t)b * 3 * HW;
    float*       offp = out_off + (size_t)b * 30 * HW;

    // ---- Halo fill: R3-proven scalar path ----
    #pragma unroll 3
    for (int p = tid; p < TDY * TDX; p += NTHREADS) {
        int r  = p / TDX;
        int cc = p - r * TDX;
        int gy = ty0 - HALO + r;
        int gx = tx0 - HALO + cc;
        float v0 = 0.f, v1 = 0.f, v2 = 0.f;   // (gy, gx)
        float u0 = 0.f, u1 = 0.f, u2 = 0.f;   // (gy, gx+1)
        bool rowok = (unsigned)gy < (unsigned)H;
        if (rowok && (unsigned)gx < (unsigned)W) {
            int gi = gy * W + gx;
            v0 = __ldg(img + gi);
            v1 = __ldg(img + gi + HW);
            v2 = __ldg(img + gi + 2 * HW);
        }
        if (rowok && (unsigned)(gx + 1) < (unsigned)W) {
            int gi = gy * W + gx + 1;
            u0 = __ldg(img + gi);
            u1 = __ldg(img + gi + HW);
            u2 = __ldg(img + gi + 2 * HW);
        }
        __half2 lo = __floats2half2_rn(v0, v1);
        __half2 hi = __floats2half2_rn(u0, u1);
        uint2 w;
        w.x = *(unsigned int*)&lo;
        w.y = *(unsigned int*)&hi;
        Ap[p] = w;
        Cp[p] = __floats2half2_rn(v2, u2);
    }
    __syncthreads();

    const float wgt = __ldg(weight) * (1.0f / 15.0f);
    const float bs  = __ldg(bias);

    // ---- Blur loop (interleaved offset stores; half2 lerp pipeline) ----
    #pragma unroll 1
    for (int i = 0; i < (TX * TY) / NTHREADS; i++) {
        int p  = i * NTHREADS + tid;
        int yl = p >> 6;              // 0..31
        int xl = p & 63;              // 0..63
        int gy = ty0 + yl;
        int gx = tx0 + xl;
        int gidx = gy * W + gx;

        float ob0 = 20.0f * __ldg(bm + gidx);        // dy scale (ch0)
        float ob1 = 20.0f * __ldg(bm + gidx + HW);   // dx scale (ch1)

        // k = 7 (t = 0): exact center sample, zero offsets
        int cbase = (yl + HALO) * TDX + (xl + HALO);
        uint2 cw = Ap[cbase];
        float2 cl = __half22float2(*(__half2*)&cw.x);
        float2 cz = __half22float2(Cp[cbase]);
        float s0 = cl.x, s1 = cl.y, s2 = cz.x;
        offp[14 * HW + gidx] = 0.f;
        offp[15 * HW + gidx] = 0.f;

        #pragma unroll
        for (int k = 0; k < 15; k++) {
            if (k == 7) continue;
            const float t = (float)(7 - k) / 7.0f;   // compile-time constant
            float oy = t * ob0;
            float ox = t * ob1;
            offp[(2 * k) * HW + gidx]     = oy;
            offp[(2 * k + 1) * HW + gidx] = ox;

            float fy  = (float)gy + oy;              // global coords = ref rounding
            float fx  = (float)gx + ox;
            float fy0 = floorf(fy);
            float fx0 = floorf(fx);
            float tyf = fy - fy0;
            float txf = fx - fx0;
            int iy = (int)fy0 - ty0 + HALO;
            int ix = (int)fx0 - tx0 + HALO;
            int base2 = iy * TDX + ix;

            uint2   w0 = Ap[base2];           // row y0: (c0,c1)@x0,x1
            uint2   w1 = Ap[base2 + TDX];     // row y1
            __half2 z0 = Cp[base2];           // c2@(x0,x1), row y0
            __half2 z1 = Cp[base2 + TDX];     // row y1

            __half2 txh = __float2half2_rn(txf);
            __half2 tyh = __float2half2_rn(tyf);

            // A path: x-lerp both rows, then y-lerp, all in half2
            __half2 a0 = *(__half2*)&w0.x;    // (c0,c1)@x0 row y0
            __half2 a1 = *(__half2*)&w0.y;    // (c0,c1)@x1 row y0
            __half2 b0h = *(__half2*)&w1.x;   // row y1
            __half2 b1h = *(__half2*)&w1.y;
            __half2 r0 = __hfma2(txh, __hsub2(a1, a0), a0);
            __half2 r1 = __hfma2(txh, __hsub2(b1h, b0h), b0h);
            __half2 ry = __hfma2(tyh, __hsub2(r1, r0), r0);
            float2 rf = __half22float2(ry);
            s0 += rf.x;
            s1 += rf.y;

            // C path: y-lerp in half2 (lanes are x0,x1), then x-lerp in fp32
            __half2 zy = __hfma2(tyh, __hsub2(z1, z0), z0);
            float2 zf = __half22float2(zy);
            s2 += zf.x;
            s2 = fmaf(txf, zf.y - zf.x, s2);
        }

        fb[gidx]          = fmaf(wgt, s0, bs);
        fb[gidx + HW]     = fmaf(wgt, s1, bs);
        fb[gidx + 2 * HW] = fmaf(wgt, s2, bs);
    }
}

extern "C" void kernel_launch(void* const* d_in, const int* in_sizes, int n_in,
                              void* d_out, int out_size)
{
    const float* fake_S  = (const float*)d_in[0];
    const float* blurmap = (const float*)d_in[1];
    const float* weight  = (const float*)d_in[2];
    const float* bias    = (const float*)d_in[3];

    float* out_fb  = (float*)d_out;
    float* out_off = (float*)d_out + (size_t)BATCH * 3 * HW;

    const int smem = TDY * TDX * 12;   // 89,856 B
    static bool configured = false;
    if (!configured) {
        cudaFuncSetAttribute(blurnet_kernel,
                             cudaFuncAttributeMaxDynamicSharedMemorySize, smem);
        configured = true;
    }

    dim3 grid(W / TX, H / TY, BATCH);   // (4, 8, 8) = 256 CTAs
    blurnet_kernel<<<grid, NTHREADS, smem>>>(fake_S, blurmap, weight, bias,
                                             out_fb, out_off);
}